// round 14
// baseline (speedup 1.0000x reference)
#include <cuda_runtime.h>
#include <cuda_bf16.h>

typedef unsigned long long ull;

#define B_ 16
#define NPTS 4096
#define PAD 8
#define DBN (NPTS + 2 * PAD)            // 4112 padded db entries
#define CTH 128                          // chamfer threads (1 query each)
#define QCH (NPTS / CTH)                 // 32 query chunks per (dir,batch)
#define CBLOCKS (2 * B_ * QCH)           // 1024 blocks
#define STH 1024                         // sort threads
#define SMEM_PREP (NPTS * (int)sizeof(float4))   // 65536
#define SMEM_CHAM (DBN * (int)sizeof(float4))    // 65792

// Scratch (no device allocations allowed)
__device__ float4 g_db[2][B_][NPTS];     // [cloud][batch] sorted-by-x {x,y,z,0.5|p|^2}
__device__ float  g_part[CBLOCKS];
__device__ int    g_count;               // zero-init; reset by last block each call

// ---------------- Pass 1: transform + pack + bitonic sort by x ----------------
// 32 blocks: cloud c (0 = X, 1 = transformed target) x batch b.
__global__ void __launch_bounds__(STH)
prep_kernel(const float* __restrict__ X, const float* __restrict__ TV,
            const float* __restrict__ TR) {
    extern __shared__ float4 s[];        // NPTS entries
    int bid = blockIdx.x;
    int b   = bid & (B_ - 1);
    int c   = bid >> 4;
    int tid = threadIdx.x;

    // Row-major [4][4] transform, row-vector convention (only used for c==1)
    const float* Tm = TR + 16 * b;
    float T00 = __ldg(Tm + 0),  T01 = __ldg(Tm + 1),  T02 = __ldg(Tm + 2),  T03 = __ldg(Tm + 3);
    float T10 = __ldg(Tm + 4),  T11 = __ldg(Tm + 5),  T12 = __ldg(Tm + 6),  T13 = __ldg(Tm + 7);
    float T20 = __ldg(Tm + 8),  T21 = __ldg(Tm + 9),  T22 = __ldg(Tm + 10), T23 = __ldg(Tm + 11);
    float T30 = __ldg(Tm + 12), T31 = __ldg(Tm + 13), T32 = __ldg(Tm + 14), T33 = __ldg(Tm + 15);

    const float* src0 = (c == 0 ? X : TV) + (size_t)b * NPTS * 3;
#pragma unroll
    for (int i = tid; i < NPTS; i += STH) {
        const float* p = src0 + 3 * i;
        float x = p[0], y = p[1], z = p[2];
        if (c == 1) {
            float u0 = x * T00 + y * T10 + z * T20 + T30;
            float u1 = x * T01 + y * T11 + z * T21 + T31;
            float u2 = x * T02 + y * T12 + z * T22 + T32;
            float w  = x * T03 + y * T13 + z * T23 + T33;
            float inv = 1.0f / w;
            x = u0 * inv; y = u1 * inv; z = u2 * inv;
        }
        s[i] = make_float4(x, y, z, 0.5f * (x * x + y * y + z * z));
    }
    __syncthreads();

    // Bitonic sort ascending by .x  (78 stages)
    for (int k = 2; k <= NPTS; k <<= 1) {
        for (int j = k >> 1; j > 0; j >>= 1) {
#pragma unroll
            for (int idx = tid; idx < NPTS; idx += STH) {
                int ixj = idx ^ j;
                if (ixj > idx) {
                    float4 a = s[idx], d = s[ixj];
                    bool up = ((idx & k) == 0);
                    if ((a.x > d.x) == up) { s[idx] = d; s[ixj] = a; }
                }
            }
            __syncthreads();
        }
    }

#pragma unroll
    for (int i = tid; i < NPTS; i += STH) g_db[c][b][i] = s[i];
}

// ---------------- Pass 2: sorted-sweep NN chamfer ----------------
// bid -> (dir, batch, qchunk). dir 0: queries = cloud0 (X), db = cloud1; dir 1 reversed.
// db in smem with PAD sentinels each side. Per query: binary search on x, then
// two 4-point-grouped expansion sweeps; break when 0.5*dx^2 - qw >= u_best
// (u = 0.5|p|^2 - p.q  ==>  d = 2*(qw+u); min over u == min over d).
__global__ void __launch_bounds__(CTH)
chamfer_kernel(float* __restrict__ out) {
    extern __shared__ float4 sdb[];      // DBN entries
    int bid = blockIdx.x;
    int qc  = bid & (QCH - 1);
    int b   = (bid >> 5) & (B_ - 1);
    int dir = bid >> 9;
    int tid = threadIdx.x;

    const float4* D = g_db[1 - dir][b];
#pragma unroll
    for (int i = tid; i < NPTS; i += CTH) sdb[PAD + i] = D[i];
    if (tid < PAD) {
        sdb[tid]           = make_float4(-1e9f, 0.0f, 0.0f, 5e17f);
        sdb[DBN - 1 - tid] = make_float4( 1e9f, 0.0f, 0.0f, 5e17f);
    }
    __syncthreads();

    float4 q = g_db[dir][b][qc * CTH + tid];   // already transformed + packed
    float qx = q.x;
    float nqx = -q.x, nqy = -q.y, nqz = -q.z, qw = q.w;

    // lower_bound over the 4096 real points (queries sorted -> warp-coherent path)
    int lo = 0, hi = NPTS;
#pragma unroll 1
    while (lo < hi) {
        int mid = (lo + hi) >> 1;
        if (sdb[PAD + mid].x < qx) lo = mid + 1; else hi = mid;
    }

    float ub = 1e30f;

    // downward sweep (groups of 4; sentinels make edge reads safe)
    int i = lo + PAD - 1;                 // in [PAD-1, NPTS+PAD-1] = [7,4103]
#pragma unroll 1
    while (true) {
        float4 p0 = sdb[i], p1 = sdb[i - 1], p2 = sdb[i - 2], p3 = sdb[i - 3];
        float u0 = fmaf(p0.x, nqx, fmaf(p0.y, nqy, fmaf(p0.z, nqz, p0.w)));
        float u1 = fmaf(p1.x, nqx, fmaf(p1.y, nqy, fmaf(p1.z, nqz, p1.w)));
        float u2 = fmaf(p2.x, nqx, fmaf(p2.y, nqy, fmaf(p2.z, nqz, p2.w)));
        float u3 = fmaf(p3.x, nqx, fmaf(p3.y, nqy, fmaf(p3.z, nqz, p3.w)));
        ub = fminf(ub, fminf(fminf(u0, u1), fminf(u2, u3)));
        float dx  = qx - p3.x;            // farthest point in this group
        float tst = fmaf(0.5f * dx, dx, -qw);
        i -= 4;
        if (tst >= ub || i < 4) break;    // index guard covers sentinel-only groups
    }

    // upward sweep
    i = lo + PAD;                         // in [8, 4104]
#pragma unroll 1
    while (true) {
        float4 p0 = sdb[i], p1 = sdb[i + 1], p2 = sdb[i + 2], p3 = sdb[i + 3];
        float u0 = fmaf(p0.x, nqx, fmaf(p0.y, nqy, fmaf(p0.z, nqz, p0.w)));
        float u1 = fmaf(p1.x, nqx, fmaf(p1.y, nqy, fmaf(p1.z, nqz, p1.w)));
        float u2 = fmaf(p2.x, nqx, fmaf(p2.y, nqy, fmaf(p2.z, nqz, p2.w)));
        float u3 = fmaf(p3.x, nqx, fmaf(p3.y, nqy, fmaf(p3.z, nqz, p3.w)));
        ub = fminf(ub, fminf(fminf(u0, u1), fminf(u2, u3)));
        float dx  = p3.x - qx;
        float tst = fmaf(0.5f * dx, dx, -qw);
        i += 4;
        if (tst >= ub || i > DBN - 4) break;   // reads stay <= DBN-1
    }

    float val = fmaxf(2.0f * (qw + ub), 0.0f);

    // block tree-sum (deterministic)
    __shared__ float red[CTH];
    __shared__ bool isLast;
    red[tid] = val;
    __syncthreads();
#pragma unroll
    for (int off = CTH / 2; off > 0; off >>= 1) {
        if (tid < off) red[tid] += red[tid + off];
        __syncthreads();
    }
    if (tid == 0) {
        g_part[bid] = red[0];
        __threadfence();
        int prev = atomicAdd(&g_count, 1);
        isLast = (prev == CBLOCKS - 1);
    }
    __syncthreads();

    if (isLast) {
        // fixed-order: each thread sums 8 strided partials, then tree
        float acc = 0.0f;
#pragma unroll
        for (int k = 0; k < CBLOCKS / CTH; k++)
            acc += g_part[tid + k * CTH];
        red[tid] = acc;
        __syncthreads();
#pragma unroll
        for (int off = CTH / 2; off > 0; off >>= 1) {
            if (tid < off) red[tid] += red[tid + off];
            __syncthreads();
        }
        if (tid == 0) {
            out[0] = red[0];
            g_count = 0;                 // reset for graph replay determinism
        }
    }
}

extern "C" void kernel_launch(void* const* d_in, const int* in_sizes, int n_in,
                              void* d_out, int out_size) {
    const float* X  = (const float*)d_in[0];  // [16,4096,3]
    const float* TV = (const float*)d_in[1];  // [16,4096,3]
    const float* TR = (const float*)d_in[2];  // [16,4,4]
    float* out = (float*)d_out;

    cudaFuncSetAttribute(prep_kernel,
                         cudaFuncAttributeMaxDynamicSharedMemorySize, SMEM_PREP);
    cudaFuncSetAttribute(chamfer_kernel,
                         cudaFuncAttributeMaxDynamicSharedMemorySize, SMEM_CHAM);

    prep_kernel<<<2 * B_, STH, SMEM_PREP>>>(X, TV, TR);
    chamfer_kernel<<<CBLOCKS, CTH, SMEM_CHAM>>>(out);
}

// round 15
// speedup vs baseline: 1.0038x; 1.0038x over previous
#include <cuda_runtime.h>
#include <cuda_bf16.h>

typedef unsigned long long ull;

#define B_ 16
#define NPTS 4096
#define PAD 8
#define DBN (NPTS + 2 * PAD)            // 4112 padded db entries
#define CTH 128                          // chamfer threads (1 query each)
#define QCH (NPTS / CTH)                 // 32 query chunks per (dir,batch)
#define CBLOCKS (2 * B_ * QCH)           // 1024 blocks
#define STH 1024                         // sort threads
#define SMEM_PREP (NPTS * (int)sizeof(float4))   // 65536
#define SMEM_CHAM (DBN * (int)sizeof(float4))    // 65792

// Scratch (no device allocations allowed)
__device__ float4 g_db[2][B_][NPTS];     // [cloud][batch] sorted-by-x {x,y,z,0.5|p|^2}
__device__ float  g_part[CBLOCKS];
__device__ int    g_count;               // zero-init; reset by last block each call

// ---------------- Pass 1: transform + pack + bitonic sort by x ----------------
// 32 blocks: cloud c (0 = X, 1 = transformed target) x batch b.
__global__ void __launch_bounds__(STH)
prep_kernel(const float* __restrict__ X, const float* __restrict__ TV,
            const float* __restrict__ TR) {
    extern __shared__ float4 s[];        // NPTS entries
    int bid = blockIdx.x;
    int b   = bid & (B_ - 1);
    int c   = bid >> 4;
    int tid = threadIdx.x;

    // Row-major [4][4] transform, row-vector convention (only used for c==1)
    const float* Tm = TR + 16 * b;
    float T00 = __ldg(Tm + 0),  T01 = __ldg(Tm + 1),  T02 = __ldg(Tm + 2),  T03 = __ldg(Tm + 3);
    float T10 = __ldg(Tm + 4),  T11 = __ldg(Tm + 5),  T12 = __ldg(Tm + 6),  T13 = __ldg(Tm + 7);
    float T20 = __ldg(Tm + 8),  T21 = __ldg(Tm + 9),  T22 = __ldg(Tm + 10), T23 = __ldg(Tm + 11);
    float T30 = __ldg(Tm + 12), T31 = __ldg(Tm + 13), T32 = __ldg(Tm + 14), T33 = __ldg(Tm + 15);

    const float* src0 = (c == 0 ? X : TV) + (size_t)b * NPTS * 3;
#pragma unroll
    for (int i = tid; i < NPTS; i += STH) {
        const float* p = src0 + 3 * i;
        float x = p[0], y = p[1], z = p[2];
        if (c == 1) {
            float u0 = x * T00 + y * T10 + z * T20 + T30;
            float u1 = x * T01 + y * T11 + z * T21 + T31;
            float u2 = x * T02 + y * T12 + z * T22 + T32;
            float w  = x * T03 + y * T13 + z * T23 + T33;
            float inv = 1.0f / w;
            x = u0 * inv; y = u1 * inv; z = u2 * inv;
        }
        s[i] = make_float4(x, y, z, 0.5f * (x * x + y * y + z * z));
    }
    __syncthreads();

    // Bitonic sort ascending by .x  (78 stages)
    for (int k = 2; k <= NPTS; k <<= 1) {
        for (int j = k >> 1; j > 0; j >>= 1) {
#pragma unroll
            for (int idx = tid; idx < NPTS; idx += STH) {
                int ixj = idx ^ j;
                if (ixj > idx) {
                    float4 a = s[idx], d = s[ixj];
                    bool up = ((idx & k) == 0);
                    if ((a.x > d.x) == up) { s[idx] = d; s[ixj] = a; }
                }
            }
            __syncthreads();
        }
    }

#pragma unroll
    for (int i = tid; i < NPTS; i += STH) g_db[c][b][i] = s[i];
}

// ---------------- Pass 2: sorted-sweep NN chamfer ----------------
// bid -> (dir, batch, qchunk). dir 0: queries = cloud0 (X), db = cloud1; dir 1 reversed.
// db in smem with PAD sentinels each side. Per query: binary search on x, then
// two 4-point-grouped expansion sweeps; break when 0.5*dx^2 - qw >= u_best
// (u = 0.5|p|^2 - p.q  ==>  d = 2*(qw+u); min over u == min over d).
__global__ void __launch_bounds__(CTH)
chamfer_kernel(float* __restrict__ out) {
    extern __shared__ float4 sdb[];      // DBN entries
    int bid = blockIdx.x;
    int qc  = bid & (QCH - 1);
    int b   = (bid >> 5) & (B_ - 1);
    int dir = bid >> 9;
    int tid = threadIdx.x;

    const float4* D = g_db[1 - dir][b];
#pragma unroll
    for (int i = tid; i < NPTS; i += CTH) sdb[PAD + i] = D[i];
    if (tid < PAD) {
        sdb[tid]           = make_float4(-1e9f, 0.0f, 0.0f, 5e17f);
        sdb[DBN - 1 - tid] = make_float4( 1e9f, 0.0f, 0.0f, 5e17f);
    }
    __syncthreads();

    float4 q = g_db[dir][b][qc * CTH + tid];   // already transformed + packed
    float qx = q.x;
    float nqx = -q.x, nqy = -q.y, nqz = -q.z, qw = q.w;

    // lower_bound over the 4096 real points (queries sorted -> warp-coherent path)
    int lo = 0, hi = NPTS;
#pragma unroll 1
    while (lo < hi) {
        int mid = (lo + hi) >> 1;
        if (sdb[PAD + mid].x < qx) lo = mid + 1; else hi = mid;
    }

    float ub = 1e30f;

    // downward sweep (groups of 4; sentinels make edge reads safe)
    int i = lo + PAD - 1;                 // in [PAD-1, NPTS+PAD-1] = [7,4103]
#pragma unroll 1
    while (true) {
        float4 p0 = sdb[i], p1 = sdb[i - 1], p2 = sdb[i - 2], p3 = sdb[i - 3];
        float u0 = fmaf(p0.x, nqx, fmaf(p0.y, nqy, fmaf(p0.z, nqz, p0.w)));
        float u1 = fmaf(p1.x, nqx, fmaf(p1.y, nqy, fmaf(p1.z, nqz, p1.w)));
        float u2 = fmaf(p2.x, nqx, fmaf(p2.y, nqy, fmaf(p2.z, nqz, p2.w)));
        float u3 = fmaf(p3.x, nqx, fmaf(p3.y, nqy, fmaf(p3.z, nqz, p3.w)));
        ub = fminf(ub, fminf(fminf(u0, u1), fminf(u2, u3)));
        float dx  = qx - p3.x;            // farthest point in this group
        float tst = fmaf(0.5f * dx, dx, -qw);
        i -= 4;
        if (tst >= ub || i < 4) break;    // index guard covers sentinel-only groups
    }

    // upward sweep
    i = lo + PAD;                         // in [8, 4104]
#pragma unroll 1
    while (true) {
        float4 p0 = sdb[i], p1 = sdb[i + 1], p2 = sdb[i + 2], p3 = sdb[i + 3];
        float u0 = fmaf(p0.x, nqx, fmaf(p0.y, nqy, fmaf(p0.z, nqz, p0.w)));
        float u1 = fmaf(p1.x, nqx, fmaf(p1.y, nqy, fmaf(p1.z, nqz, p1.w)));
        float u2 = fmaf(p2.x, nqx, fmaf(p2.y, nqy, fmaf(p2.z, nqz, p2.w)));
        float u3 = fmaf(p3.x, nqx, fmaf(p3.y, nqy, fmaf(p3.z, nqz, p3.w)));
        ub = fminf(ub, fminf(fminf(u0, u1), fminf(u2, u3)));
        float dx  = p3.x - qx;
        float tst = fmaf(0.5f * dx, dx, -qw);
        i += 4;
        if (tst >= ub || i > DBN - 4) break;   // reads stay <= DBN-1
    }

    float val = fmaxf(2.0f * (qw + ub), 0.0f);

    // block tree-sum (deterministic)
    __shared__ float red[CTH];
    __shared__ bool isLast;
    red[tid] = val;
    __syncthreads();
#pragma unroll
    for (int off = CTH / 2; off > 0; off >>= 1) {
        if (tid < off) red[tid] += red[tid + off];
        __syncthreads();
    }
    if (tid == 0) {
        g_part[bid] = red[0];
        __threadfence();
        int prev = atomicAdd(&g_count, 1);
        isLast = (prev == CBLOCKS - 1);
    }
    __syncthreads();

    if (isLast) {
        // fixed-order: each thread sums 8 strided partials, then tree
        float acc = 0.0f;
#pragma unroll
        for (int k = 0; k < CBLOCKS / CTH; k++)
            acc += g_part[tid + k * CTH];
        red[tid] = acc;
        __syncthreads();
#pragma unroll
        for (int off = CTH / 2; off > 0; off >>= 1) {
            if (tid < off) red[tid] += red[tid + off];
            __syncthreads();
        }
        if (tid == 0) {
            out[0] = red[0];
            g_count = 0;                 // reset for graph replay determinism
        }
    }
}

extern "C" void kernel_launch(void* const* d_in, const int* in_sizes, int n_in,
                              void* d_out, int out_size) {
    const float* X  = (const float*)d_in[0];  // [16,4096,3]
    const float* TV = (const float*)d_in[1];  // [16,4096,3]
    const float* TR = (const float*)d_in[2];  // [16,4,4]
    float* out = (float*)d_out;

    cudaFuncSetAttribute(prep_kernel,
                         cudaFuncAttributeMaxDynamicSharedMemorySize, SMEM_PREP);
    cudaFuncSetAttribute(chamfer_kernel,
                         cudaFuncAttributeMaxDynamicSharedMemorySize, SMEM_CHAM);

    prep_kernel<<<2 * B_, STH, SMEM_PREP>>>(X, TV, TR);
    chamfer_kernel<<<CBLOCKS, CTH, SMEM_CHAM>>>(out);
}

// round 16
// speedup vs baseline: 1.7451x; 1.7386x over previous
#include <cuda_runtime.h>
#include <cuda_bf16.h>

#define B_    16
#define NPTS  4096
#define NB    512                 // x-buckets over [-8, 8)
#define XMIN  (-8.0f)
#define BW    0.03125f            // 16 / 512
#define INVW  32.0f
#define PTH   512                 // prep threads
#define CTH   128                 // chamfer threads
#define QPT   2                   // queries per thread
#define QPB   (CTH * QPT)         // 256 queries per block
#define QCH   (NPTS / QPB)        // 16 chunks per (dir,batch)
#define CBLOCKS (2 * B_ * QCH)    // 512 blocks

#define SMEM_PREP (NPTS * (int)sizeof(float4) + (2 * NB + 1) * (int)sizeof(int))
#define SMEM_CHAM (NPTS * (int)sizeof(float4) + (NB + 1) * (int)sizeof(int))

// Scratch (no device allocations allowed)
__device__ float4 g_db[2][B_][NPTS];      // bucket-ordered {x,y,z, 0.5|p|^2}
__device__ int    g_off[2][B_][NB + 1];   // CSR bucket offsets
__device__ double g_part[CBLOCKS];
__device__ int    g_count;                // zero-init; reset by last block

__device__ __forceinline__ int bucketOf(float x) {
    int bk = (int)floorf((x - XMIN) * INVW);
    return min(max(bk, 0), NB - 1);       // clamp: end-buckets stay conservative
}

// ---------------- Pass 1: transform + pack + counting-sort by x-bucket ----------
// 32 blocks: cloud c (0 = X, 1 = transformed target) x batch b.
__global__ void __launch_bounds__(PTH)
prep_kernel(const float* __restrict__ X, const float* __restrict__ TV,
            const float* __restrict__ TR) {
    extern __shared__ char smraw[];
    float4* s   = (float4*)smraw;          // NPTS packed points
    int*    cnt = (int*)(s + NPTS);        // NB counters (reused for scatter)
    int*    off = cnt + NB;                // NB+1 offsets

    int bid = blockIdx.x;
    int b   = bid & (B_ - 1);
    int c   = bid >> 4;
    int tid = threadIdx.x;

    // Row-major [4][4], row-vector convention (used only for c==1)
    const float* Tm = TR + 16 * b;
    float T00 = __ldg(Tm + 0),  T01 = __ldg(Tm + 1),  T02 = __ldg(Tm + 2),  T03 = __ldg(Tm + 3);
    float T10 = __ldg(Tm + 4),  T11 = __ldg(Tm + 5),  T12 = __ldg(Tm + 6),  T13 = __ldg(Tm + 7);
    float T20 = __ldg(Tm + 8),  T21 = __ldg(Tm + 9),  T22 = __ldg(Tm + 10), T23 = __ldg(Tm + 11);
    float T30 = __ldg(Tm + 12), T31 = __ldg(Tm + 13), T32 = __ldg(Tm + 14), T33 = __ldg(Tm + 15);

    if (tid < NB) cnt[tid] = 0;
    __syncthreads();

    const float* src = (c == 0 ? X : TV) + (size_t)b * NPTS * 3;
#pragma unroll
    for (int i = tid; i < NPTS; i += PTH) {
        const float* p = src + 3 * i;
        float x = p[0], y = p[1], z = p[2];
        if (c == 1) {
            float u0 = x * T00 + y * T10 + z * T20 + T30;
            float u1 = x * T01 + y * T11 + z * T21 + T31;
            float u2 = x * T02 + y * T12 + z * T22 + T32;
            float w  = x * T03 + y * T13 + z * T23 + T33;
            float inv = 1.0f / w;
            x = u0 * inv; y = u1 * inv; z = u2 * inv;
        }
        s[i] = make_float4(x, y, z, 0.5f * (x * x + y * y + z * z));
        atomicAdd(&cnt[bucketOf(x)], 1);
    }
    __syncthreads();

    // Hillis-Steele inclusive scan of cnt -> off[1..NB]; off[0]=0 (in-place on off+1)
    if (tid < NB) off[tid + 1] = cnt[tid];
    if (tid == 0) off[0] = 0;
    __syncthreads();
#pragma unroll
    for (int st = 1; st < NB; st <<= 1) {
        int v = 0;
        if (tid < NB) {
            v = off[tid + 1];
            if (tid >= st) v += off[tid + 1 - st];
        }
        __syncthreads();
        if (tid < NB) off[tid + 1] = v;
        __syncthreads();
    }
    if (tid < NB) cnt[tid] = 0;            // reuse as scatter cursors
    __syncthreads();

#pragma unroll
    for (int i = tid; i < NPTS; i += PTH) {
        float4 p = s[i];
        int bk = bucketOf(p.x);
        int pos = off[bk] + atomicAdd(&cnt[bk], 1);
        g_db[c][b][pos] = p;
    }
    for (int i = tid; i <= NB; i += PTH) g_off[c][b][i] = off[i];
}

// ---------------- Pass 2: bucket-pruned NN chamfer, warp-uniform scan ----------
// bid -> (dir, batch, qchunk). Each thread owns 2 adjacent (bucket-ordered)
// queries; each WARP scans a warp-uniform sequence of whole buckets (home range,
// then down / up sweeps), breaking only when ALL lanes' bucket-edge bound proves
// no improvement:  u_p >= 0.5*dx_edge^2 - qw  for every point p in that bucket.
#define SCAN_BUCKET(bb)                                                          \
    {                                                                            \
        int sB = soff[bb], eB = soff[(bb) + 1];                                  \
        for (int i = sB; i < eB; i++) {                                          \
            float4 p = sdb[i];                                                   \
            float t0 = fmaf(p.z, nz0, p.w);                                      \
            float t1 = fmaf(p.z, nz1, p.w);                                      \
            t0 = fmaf(p.y, ny0, t0);                                             \
            t1 = fmaf(p.y, ny1, t1);                                             \
            t0 = fmaf(p.x, nx0, t0);                                             \
            t1 = fmaf(p.x, nx1, t1);                                             \
            ub0 = fminf(ub0, t0);                                                \
            ub1 = fminf(ub1, t1);                                                \
        }                                                                        \
    }

__global__ void __launch_bounds__(CTH)
chamfer_kernel(float* __restrict__ out) {
    extern __shared__ char smraw[];
    float4* sdb  = (float4*)smraw;         // NPTS bucket-ordered db points
    int*    soff = (int*)(sdb + NPTS);     // NB+1
    __shared__ double red[CTH];
    __shared__ bool isLast;

    int bid = blockIdx.x;
    int qc  = bid & (QCH - 1);
    int b   = (bid >> 4) & (B_ - 1);
    int dir = bid >> 8;
    int tid = threadIdx.x;

    const float4* D = g_db[1 - dir][b];
#pragma unroll
    for (int i = tid; i < NPTS; i += CTH) sdb[i] = D[i];
    const int* O = g_off[1 - dir][b];
#pragma unroll
    for (int i = tid; i <= NB; i += CTH) soff[i] = O[i];
    __syncthreads();

    int qi = qc * QPB + 2 * tid;
    float4 q0 = g_db[dir][b][qi];
    float4 q1 = g_db[dir][b][qi + 1];
    float nx0 = -q0.x, ny0 = -q0.y, nz0 = -q0.z, qw0 = q0.w;
    float nx1 = -q1.x, ny1 = -q1.y, nz1 = -q1.z, qw1 = q1.w;
    float ub0 = 1e30f, ub1 = 1e30f;

    int qb0 = bucketOf(q0.x), qb1 = bucketOf(q1.x);
    int bmin = min(qb0, qb1), bmax = max(qb0, qb1);
#pragma unroll
    for (int o = 16; o; o >>= 1) {
        bmin = min(bmin, __shfl_xor_sync(0xffffffffu, bmin, o));
        bmax = max(bmax, __shfl_xor_sync(0xffffffffu, bmax, o));
    }

    // home range (seeds ub)
#pragma unroll 1
    for (int bb = bmin; bb <= bmax; bb++) SCAN_BUCKET(bb);

    // downward sweep
#pragma unroll 1
    for (int bb = bmin - 1; bb >= 0; bb--) {
        float hi = XMIN + (float)(bb + 1) * BW;       // upper edge of bucket bb
        float d0 = fmaxf(q0.x - hi, 0.0f);
        float d1 = fmaxf(q1.x - hi, 0.0f);
        bool ok = (fmaf(0.5f * d0, d0, -qw0) >= ub0) &&
                  (fmaf(0.5f * d1, d1, -qw1) >= ub1);
        if (__all_sync(0xffffffffu, ok)) break;
        SCAN_BUCKET(bb);
    }

    // upward sweep
#pragma unroll 1
    for (int bb = bmax + 1; bb < NB; bb++) {
        float lo = XMIN + (float)bb * BW;             // lower edge of bucket bb
        float d0 = fmaxf(lo - q0.x, 0.0f);
        float d1 = fmaxf(lo - q1.x, 0.0f);
        bool ok = (fmaf(0.5f * d0, d0, -qw0) >= ub0) &&
                  (fmaf(0.5f * d1, d1, -qw1) >= ub1);
        if (__all_sync(0xffffffffu, ok)) break;
        SCAN_BUCKET(bb);
    }

    // d = 2*(qw + u), clamped at 0 — matches reference formulation
    double acc = (double)fmaxf(2.0f * (qw0 + ub0), 0.0f)
               + (double)fmaxf(2.0f * (qw1 + ub1), 0.0f);

    red[tid] = acc;
    __syncthreads();
#pragma unroll
    for (int off = CTH / 2; off > 0; off >>= 1) {
        if (tid < off) red[tid] += red[tid + off];
        __syncthreads();
    }
    if (tid == 0) {
        g_part[bid] = red[0];
        __threadfence();
        int prev = atomicAdd(&g_count, 1);
        isLast = (prev == CBLOCKS - 1);
    }
    __syncthreads();

    if (isLast) {
        double a = 0.0;
#pragma unroll
        for (int k = 0; k < CBLOCKS / CTH; k++)
            a += g_part[tid + k * CTH];
        red[tid] = a;
        __syncthreads();
#pragma unroll
        for (int off = CTH / 2; off > 0; off >>= 1) {
            if (tid < off) red[tid] += red[tid + off];
            __syncthreads();
        }
        if (tid == 0) {
            out[0] = (float)red[0];
            g_count = 0;                   // reset for graph replay determinism
        }
    }
}

extern "C" void kernel_launch(void* const* d_in, const int* in_sizes, int n_in,
                              void* d_out, int out_size) {
    const float* X  = (const float*)d_in[0];  // [16,4096,3]
    const float* TV = (const float*)d_in[1];  // [16,4096,3]
    const float* TR = (const float*)d_in[2];  // [16,4,4]
    float* out = (float*)d_out;

    cudaFuncSetAttribute(prep_kernel,
                         cudaFuncAttributeMaxDynamicSharedMemorySize, SMEM_PREP);
    cudaFuncSetAttribute(chamfer_kernel,
                         cudaFuncAttributeMaxDynamicSharedMemorySize, SMEM_CHAM);

    prep_kernel<<<2 * B_, PTH, SMEM_PREP>>>(X, TV, TR);
    chamfer_kernel<<<CBLOCKS, CTH, SMEM_CHAM>>>(out);
}